// round 3
// baseline (speedup 1.0000x reference)
#include <cuda_runtime.h>

#define BB 32
#define PP 65536
#define TT 16
#define NB 2048
#define BLK 256
#define IPT 8
#define NBLK (PP/(BLK*IPT))    // 32 blocks per batch in k1
#define IPTF 16
#define NBLKF (PP/(256*IPTF))  // 16 blocks per batch in filters

// ---------------- device scratch ----------------
__device__ unsigned int       g_mine[BB][PP];
__device__ unsigned long long g_bp[BB][NBLK][TT];
__device__ int    g_h1c[BB][NB];
__device__ int    g_h2c[BB][NB];
__device__ int    g_h3c[BB][NB];
__device__ int    g_poscnt[BB];
__device__ double g_posloss[BB];
__device__ double g_lossl;
__device__ unsigned g_pref0[BB];
__device__ int    g_R1[BB];
__device__ unsigned g_pref22[BB];
__device__ int    g_R2[BB];
__device__ double g_sgt[BB];
__device__ double g_topsum[BB];
__device__ int    g_ctr;

// ---------------- shared helpers (identical in k1 and k_fix) ----------------
// 2-chain argmax over truths + optional per-truth candidate tracking.
template<bool TRACK>
__device__ __forceinline__ void match2(
    float4 pr, const float4* tr, const float* cA,
    float& bi, float& bd, int& bti,
    float* ti_, float* td_, unsigned* tp_, unsigned p)
{
    float hx = __fmul_rn(0.5f, pr.z), hy = __fmul_rn(0.5f, pr.w);
    float bx0 = __fsub_rn(pr.x, hx), by0 = __fsub_rn(pr.y, hy);
    float bx1 = __fadd_rn(pr.x, hx), by1 = __fadd_rn(pr.y, hy);
    float areaB = __fmul_rn(__fsub_rn(bx1, bx0), __fsub_rn(by1, by0));
    float bi0 = -1.0f, bd0 = 1.0f, bi1 = -1.0f, bd1 = 1.0f;
    int bt0 = 0, bt1 = 1;
#pragma unroll
    for (int t = 0; t < TT; t += 2) {
        {
            float4 a = tr[t];
            float w = fmaxf(__fsub_rn(fminf(a.z, bx1), fmaxf(a.x, bx0)), 0.0f);
            float h = fmaxf(__fsub_rn(fminf(a.w, by1), fmaxf(a.y, by0)), 0.0f);
            float inter = __fmul_rn(w, h);
            float den = __fsub_rn(__fadd_rn(cA[t], areaB), inter);
            if (__fmul_rn(inter, bd0) > __fmul_rn(bi0, den)) { bi0 = inter; bd0 = den; bt0 = t; }
            if (TRACK) {
                if (__fmul_rn(inter, td_[t]) > __fmul_rn(ti_[t], den)) {
                    ti_[t] = inter; td_[t] = den; tp_[t] = p;
                }
            }
        }
        {
            int t1 = t + 1;
            float4 a = tr[t1];
            float w = fmaxf(__fsub_rn(fminf(a.z, bx1), fmaxf(a.x, bx0)), 0.0f);
            float h = fmaxf(__fsub_rn(fminf(a.w, by1), fmaxf(a.y, by0)), 0.0f);
            float inter = __fmul_rn(w, h);
            float den = __fsub_rn(__fadd_rn(cA[t1], areaB), inter);
            if (__fmul_rn(inter, bd1) > __fmul_rn(bi1, den)) { bi1 = inter; bd1 = den; bt1 = t1; }
            if (TRACK) {
                if (__fmul_rn(inter, td_[t1]) > __fmul_rn(ti_[t1], den)) {
                    ti_[t1] = inter; td_[t1] = den; tp_[t1] = p;
                }
            }
        }
    }
    if (__fmul_rn(bi1, bd0) > __fmul_rn(bi0, bd1)) { bi = bi1; bd = bd1; bti = bt1; }
    else                                            { bi = bi0; bd = bd0; bti = bt0; }
}

__device__ __forceinline__ float lse2(float2 c) {
    return __fadd_rn(fmaxf(c.x, c.y),
                     __logf(__fadd_rn(1.0f, __expf(-fabsf(__fsub_rn(c.x, c.y))))));
}

__device__ __forceinline__ float loc_sl1(float4 ld, float4 a, float4 pr) {
    float gx = ((a.x + a.z) * 0.5f - pr.x) / (0.1f * pr.z);
    float gy = ((a.y + a.w) * 0.5f - pr.y) / (0.1f * pr.w);
    float gw = __logf((a.z - a.x) / pr.z) / 0.2f;
    float gh = __logf((a.w - a.y) / pr.w) / 0.2f;
    float d0 = fabsf(ld.x - gx), d1 = fabsf(ld.y - gy);
    float d2 = fabsf(ld.z - gw), d3 = fabsf(ld.w - gh);
    return (d0 < 1.f ? 0.5f * d0 * d0 : d0 - 0.5f)
         + (d1 < 1.f ? 0.5f * d1 * d1 : d1 - 0.5f)
         + (d2 < 1.f ? 0.5f * d2 * d2 : d2 - 0.5f)
         + (d3 < 1.f ? 0.5f * d3 * d3 : d3 - 0.5f);
}

// Parallel descending radix-select: find bin where descending cumulative count
// reaches R. Writes *s_idx (bin) and *s_rem (R minus count of strictly-higher bins).
// lc_out[k] = count at idx NB-1-(tid*8+k). s_w is 8-int shared scratch.
__device__ __forceinline__ void scan_desc(const int* __restrict__ cnt, int R, int tid,
                                          int* s_w, unsigned* s_idx, int* s_rem,
                                          int* lc_out)
{
    int lane = tid & 31, w = tid >> 5;
    int base = tid * 8;
    int c = 0;
#pragma unroll
    for (int k = 0; k < 8; k++) { lc_out[k] = cnt[NB - 1 - (base + k)]; c += lc_out[k]; }
    int inc = c;
#pragma unroll
    for (int o = 1; o < 32; o <<= 1) {
        int n = __shfl_up_sync(0xFFFFFFFFu, inc, o);
        if (lane >= o) inc += n;
    }
    if (lane == 31) s_w[w] = inc;
    __syncthreads();
    if (tid == 0) {
        int rc = 0;
        for (int i = 0; i < 8; i++) { int v = s_w[i]; s_w[i] = rc; rc += v; }
    }
    __syncthreads();
    int epc = s_w[w] + inc - c;
    if (epc < R && R <= epc + c) {
        int rc = epc;
#pragma unroll
        for (int k = 0; k < 8; k++) {
            int idx = NB - 1 - (base + k);
            if (rc + lc_out[k] >= R) { *s_idx = (unsigned)idx; *s_rem = R - rc; break; }
            rc += lc_out[k];
        }
    }
    __syncthreads();
}

// ---------------- zero kernels (split so launch #6 == k1 for ncu -s 5 -c 1) ----------------
__global__ void k_zero_a() { int g = blockIdx.x * 256 + threadIdx.x;
    for (int i = g; i < BB * NB; i += 16384) ((int*)g_h1c)[i] = 0; }
__global__ void k_zero_b() { int g = blockIdx.x * 256 + threadIdx.x;
    for (int i = g; i < BB * NB; i += 16384) ((int*)g_h2c)[i] = 0; }
__global__ void k_zero_c() { int g = blockIdx.x * 256 + threadIdx.x;
    for (int i = g; i < BB * NB; i += 16384) ((int*)g_h3c)[i] = 0; }
__global__ void k_zero_d() { int g = threadIdx.x;
    if (g < BB) { g_poscnt[g] = 0; g_posloss[g] = 0.0; } }
__global__ void k_zero_e() { int g = threadIdx.x;
    if (g < BB) g_sgt[g] = 0.0;
    if (g == 0) { g_lossl = 0.0; g_ctr = 0; } }

// ---------------- K1: fused match + losses + level-1 histogram ----------------
__global__ void __launch_bounds__(BLK) k1(const float4* __restrict__ loc,
                                          const float2* __restrict__ conf,
                                          const float4* __restrict__ priors,
                                          const float*  __restrict__ targets) {
    int b = blockIdx.y, tid = threadIdx.x;
    int lane = tid & 31;
    __shared__ float4 tr[TT];
    __shared__ float  cA[TT];
    __shared__ int    sc[NB];
    __shared__ unsigned long long skey[TT];
    for (int i = tid; i < NB; i += BLK) sc[i] = 0;
    if (tid < TT) {
        const float* tb = targets + (b * TT + tid) * 5;
        float4 v = make_float4(tb[0], tb[1], tb[2], tb[3]);
        tr[tid] = v;
        cA[tid] = __fmul_rn(__fsub_rn(v.z, v.x), __fsub_rn(v.w, v.y));
        skey[tid] = 0ull;
    }
    __syncthreads();

    float ti_[TT], td_[TT]; unsigned tp_[TT];
#pragma unroll
    for (int t = 0; t < TT; t++) { ti_[t] = -1.0f; td_[t] = 1.0f; tp_[t] = 0u; }

    float lossl = 0.0f, ploss = 0.0f;
    int pcnt = 0;
    int pbase = blockIdx.x * (BLK * IPT);
#pragma unroll 1
    for (int i = 0; i < IPT; i++) {
        int p = pbase + i * BLK + tid;
        float4 pr = priors[p];
        float bi, bd; int bti;
        match2<true>(pr, tr, cA, bi, bd, bti, ti_, td_, tp_, (unsigned)p);

        bool pos = (__fmul_rn(2.0f, bi) >= bd);
        float2 c = conf[(size_t)b * PP + p];
        float lse = lse2(c);
        float mv = pos ? 0.0f : __fsub_rn(lse, c.x);
        unsigned bits = __float_as_uint(mv);
        g_mine[b][p] = bits;
        unsigned bin = bits >> 21;
        unsigned peers = __match_any_sync(0xFFFFFFFFu, bin);
        if (lane == __ffs(peers) - 1) atomicAdd(&sc[bin], __popc(peers));
        if (pos) {
            pcnt++;
            ploss += __fsub_rn(lse, c.y);
            lossl += loc_sl1(loc[(size_t)b * PP + p], tr[bti], pr);
        }
    }

#pragma unroll
    for (int t = 0; t < TT; t++) {
        float iou = ti_[t] / td_[t];
        unsigned long long key =
            ((unsigned long long)__float_as_uint(iou) << 32) |
            (unsigned long long)(0xFFFFFFFFu - tp_[t]);
#pragma unroll
        for (int o = 16; o > 0; o >>= 1) {
            unsigned long long ok = __shfl_down_sync(0xFFFFFFFFu, key, o);
            if (ok > key) key = ok;
        }
        if (lane == 0) atomicMax(&skey[t], key);
    }

#pragma unroll
    for (int o = 16; o > 0; o >>= 1) {
        lossl += __shfl_down_sync(0xFFFFFFFFu, lossl, o);
        ploss += __shfl_down_sync(0xFFFFFFFFu, ploss, o);
        pcnt  += __shfl_down_sync(0xFFFFFFFFu, pcnt, o);
    }
    if (lane == 0) {
        if (lossl != 0.0f) atomicAdd(&g_lossl, (double)lossl);
        if (pcnt) {
            atomicAdd(&g_poscnt[b], pcnt);
            atomicAdd(&g_posloss[b], (double)ploss);
        }
    }
    __syncthreads();
    if (tid < TT) g_bp[b][blockIdx.x][tid] = skey[tid];
    for (int i = tid; i < NB; i += BLK) {
        int cv = sc[i];
        if (cv) atomicAdd(&g_h1c[b][i], cv);
    }
}

// ---------------- K2: best-prior override fixup (warp per batch) ----------------
__global__ void __launch_bounds__(1024) k_fix(const float4* __restrict__ loc,
                                              const float2* __restrict__ conf,
                                              const float4* __restrict__ priors,
                                              const float*  __restrict__ targets) {
    int tid = threadIdx.x;
    int b = tid >> 5, lane = tid & 31;
    __shared__ float4 str[BB][TT];
    __shared__ float  scA[BB][TT];
    if (tid < BB * TT) {
        int bb = tid / TT, t = tid % TT;
        const float* tb = targets + (bb * TT + t) * 5;
        float4 v = make_float4(tb[0], tb[1], tb[2], tb[3]);
        str[bb][t] = v;
        scA[bb][t] = __fmul_rn(__fsub_rn(v.z, v.x), __fsub_rn(v.w, v.y));
    }
    __syncthreads();

    unsigned ps[TT];
#pragma unroll
    for (int t = 0; t < TT; t++) {
        unsigned long long k = g_bp[b][lane][t];   // lane == block index (NBLK==32)
#pragma unroll
        for (int o = 16; o > 0; o >>= 1) {
            unsigned long long ok = __shfl_down_sync(0xFFFFFFFFu, k, o);
            if (ok > k) k = ok;
        }
        k = __shfl_sync(0xFFFFFFFFu, k, 0);
        ps[t] = 0xFFFFFFFFu - (unsigned)(k & 0xFFFFFFFFull);
    }
    if (lane != 0) return;

    for (int t = 0; t < TT; t++) {
        bool last = true;
        for (int t2 = t + 1; t2 < TT; t2++)
            if (ps[t2] == ps[t]) { last = false; break; }
        if (!last) continue;                 // last write wins
        unsigned p = ps[t];
        float4 pr = priors[p];
        float bi, bd; int bti;
        match2<false>(pr, str[b], scA[b], bi, bd, bti, nullptr, nullptr, nullptr, 0u);
        bool pos_old = (__fmul_rn(2.0f, bi) >= bd);
        float2 c = conf[(size_t)b * PP + p];
        float lse = lse2(c);
        float4 ld = loc[(size_t)b * PP + p];
        float sl_new = loc_sl1(ld, str[b][t], pr);
        double dl = 0.0;
        if (pos_old) {
            if (bti != t) dl = (double)sl_new - (double)loc_sl1(ld, str[b][bti], pr);
        } else {
            dl = (double)sl_new;
            g_poscnt[b] += 1;
            g_posloss[b] += (double)__fsub_rn(lse, c.y);
            float mo = __fsub_rn(lse, c.x);      // bit-identical to k1's mv
            unsigned ob = __float_as_uint(mo) >> 21;
            g_h1c[b][ob] -= 1;
            g_h1c[b][0]  += 1;
            g_mine[b][p] = 0u;
        }
        if (dl != 0.0) atomicAdd(&g_lossl, dl);
    }
}

// ---------------- filter A: in-block level-0 select + level-1 histogram ----------------
__global__ void __launch_bounds__(256) k_fa() {
    int b = blockIdx.y, tid = threadIdx.x, lane = tid & 31;
    __shared__ int sc[NB];
    __shared__ int s_w[8];
    __shared__ unsigned s_idx;
    __shared__ int s_rem;
    for (int i = tid; i < NB; i += 256) sc[i] = 0;

    int k3 = 3 * g_poscnt[b];
    int R = (k3 < PP - 1) ? k3 : (PP - 1);
    int lc[8];
    scan_desc(g_h1c[b], R, tid, s_w, &s_idx, &s_rem, lc);
    unsigned pref = s_idx;

    int pbase = blockIdx.x * (256 * IPTF);
#pragma unroll
    for (int i = 0; i < IPTF; i++) {
        unsigned bits = g_mine[b][pbase + i * 256 + tid];
        if ((bits >> 21) == pref) atomicAdd(&sc[(bits >> 10) & 0x7FFu], 1);
    }
    __syncthreads();
    for (int i = tid; i < NB; i += 256)
        if (sc[i]) atomicAdd(&g_h2c[b][i], sc[i]);
    if (tid == 0) { g_pref0[b] = pref; g_R1[b] = s_rem; }
    (void)lane;
}

// ---------------- filter B: in-block level-1 select + level-2 hist + upper sum ----------------
__global__ void __launch_bounds__(256) k_fb() {
    int b = blockIdx.y, tid = threadIdx.x, lane = tid & 31;
    __shared__ int sc[NB];
    __shared__ int s_w[8];
    __shared__ unsigned s_idx;
    __shared__ int s_rem;
    for (int i = tid; i < NB; i += 256) sc[i] = 0;

    int lc[8];
    scan_desc(g_h2c[b], g_R1[b], tid, s_w, &s_idx, &s_rem, lc);
    unsigned pref22 = (g_pref0[b] << 11) | s_idx;

    float fsum = 0.0f;
    int pbase = blockIdx.x * (256 * IPTF);
#pragma unroll
    for (int i = 0; i < IPTF; i++) {
        unsigned bits = g_mine[b][pbase + i * 256 + tid];
        unsigned top = bits >> 10;
        if (top == pref22) atomicAdd(&sc[bits & 0x3FFu], 1);
        else if (top > pref22) fsum += __uint_as_float(bits);
    }
    __syncthreads();
    for (int i = tid; i < NB; i += 256)
        if (sc[i]) atomicAdd(&g_h3c[b][i], sc[i]);
#pragma unroll
    for (int o = 16; o > 0; o >>= 1)
        fsum += __shfl_down_sync(0xFFFFFFFFu, fsum, o);
    if (lane == 0 && fsum != 0.0f) atomicAdd(&g_sgt[b], (double)fsum);
    if (tid == 0) { g_pref22[b] = pref22; g_R2[b] = s_rem; }
}

// ---------------- last: level-2 select + exact top-K sum + final combine ----------------
__global__ void __launch_bounds__(256) k_last(float* __restrict__ out) {
    int b = blockIdx.x, tid = threadIdx.x;
    __shared__ int s_w[8];
    __shared__ unsigned s_idx;
    __shared__ int s_rem;
    __shared__ double wsum[8];
    __shared__ int s_last;

    int lc[8];
    scan_desc(g_h3c[b], g_R2[b], tid, s_w, &s_idx, &s_rem, lc);
    unsigned pref = g_pref22[b];
    unsigned idx3 = s_idx;
    int R3 = s_rem;

    double s = 0.0;
    int base = tid * 8;
#pragma unroll
    for (int k = 0; k < 8; k++) {
        unsigned idx = (unsigned)(NB - 1 - (base + k));
        if (idx > idx3 && lc[k])
            s += (double)lc[k] * (double)__uint_as_float((pref << 10) | idx);
    }
#pragma unroll
    for (int o = 16; o > 0; o >>= 1)
        s += __shfl_down_sync(0xFFFFFFFFu, s, o);
    if ((tid & 31) == 0) wsum[tid >> 5] = s;
    __syncthreads();
    if (tid == 0) {
        double tot = 0.0;
        for (int w = 0; w < 8; w++) tot += wsum[w];
        g_topsum[b] = g_sgt[b] + tot +
                      (double)R3 * (double)__uint_as_float((pref << 10) | idx3);
        __threadfence();
        int done = atomicAdd(&g_ctr, 1);
        s_last = (done == BB - 1) ? 1 : 0;
    }
    __syncthreads();
    if (s_last) {
        __threadfence();
        if (tid < 32) {
            int np = g_poscnt[tid];
            double lc2 = g_posloss[tid] + g_topsum[tid];
#pragma unroll
            for (int o = 16; o > 0; o >>= 1) {
                np  += __shfl_down_sync(0xFFFFFFFFu, np, o);
                lc2 += __shfl_down_sync(0xFFFFFFFFu, lc2, o);
            }
            if (tid == 0) {
                double N = (double)np;
                out[0] = (float)(g_lossl / N);
                out[1] = (float)(lc2 / N);
            }
        }
    }
}

// ---------------- launch ----------------
extern "C" void kernel_launch(void* const* d_in, const int* in_sizes, int n_in,
                              void* d_out, int out_size) {
    const float4* loc     = (const float4*)d_in[0];
    const float2* conf    = (const float2*)d_in[1];
    const float4* priors  = (const float4*)d_in[2];
    const float*  targets = (const float*)d_in[3];
    float* out = (float*)d_out;

    k_zero_a<<<64, 256>>>();
    k_zero_b<<<64, 256>>>();
    k_zero_c<<<64, 256>>>();
    k_zero_d<<<1, 64>>>();
    k_zero_e<<<1, 64>>>();
    dim3 g1(NBLK, BB);
    k1<<<g1, BLK>>>(loc, conf, priors, targets);   // launch #6 → ncu captures this
    k_fix<<<1, 1024>>>(loc, conf, priors, targets);
    dim3 gf(NBLKF, BB);
    k_fa<<<gf, 256>>>();
    k_fb<<<gf, 256>>>();
    k_last<<<BB, 256>>>(out);
}

// round 4
// speedup vs baseline: 1.7025x; 1.7025x over previous
#include <cuda_runtime.h>

#define BB 32
#define PP 65536
#define TT 16
#define NB 2048
#define BLK 256
#define IPT 16
#define NBLK (PP/(BLK*IPT))    // 16 blocks per batch in k1
#define IPTF 16
#define NBLKF (PP/(256*IPTF))  // 16 blocks per batch in filters

// ---------------- device scratch ----------------
__device__ unsigned int       g_mine[BB][PP];
__device__ unsigned long long g_bp[BB][NBLK][TT];
__device__ int    g_h1c[BB][NB];
__device__ int    g_h2c[BB][NB];
__device__ int    g_h3c[BB][NB];
__device__ int    g_poscnt[BB];
__device__ double g_posloss[BB];
__device__ double g_lossl;
__device__ unsigned g_pref0[BB];
__device__ int    g_R1[BB];
__device__ unsigned g_pref22[BB];
__device__ int    g_R2[BB];
__device__ double g_sgt[BB];
__device__ double g_topsum[BB];
__device__ int    g_ctr;

// ---------------- shared helpers (bit-identical in k1 and k_fix) ----------------
template<bool TRACK>
__device__ __forceinline__ void match_one_prior(
    float4 pr, const float4* tr, const float* cA,
    float& bi, float& bd, int& bti,
    float* ti_, float* td_, unsigned* tp_, unsigned p)
{
    float hx = __fmul_rn(0.5f, pr.z), hy = __fmul_rn(0.5f, pr.w);
    float bx0 = __fsub_rn(pr.x, hx), by0 = __fsub_rn(pr.y, hy);
    float bx1 = __fadd_rn(pr.x, hx), by1 = __fadd_rn(pr.y, hy);
    float areaB = __fmul_rn(__fsub_rn(bx1, bx0), __fsub_rn(by1, by0));
    bi = -1.0f; bd = 1.0f; bti = 0;
#pragma unroll
    for (int t = 0; t < TT; t++) {
        float4 a = tr[t];
        float w = fmaxf(__fsub_rn(fminf(a.z, bx1), fmaxf(a.x, bx0)), 0.0f);
        float h = fmaxf(__fsub_rn(fminf(a.w, by1), fmaxf(a.y, by0)), 0.0f);
        float inter = __fmul_rn(w, h);
        float den = __fsub_rn(__fadd_rn(cA[t], areaB), inter);
        if (__fmul_rn(inter, bd) > __fmul_rn(bi, den)) { bi = inter; bd = den; bti = t; }
        if (TRACK) {
            if (__fmul_rn(inter, td_[t]) > __fmul_rn(ti_[t], den)) {
                ti_[t] = inter; td_[t] = den; tp_[t] = p;
            }
        }
    }
}

__device__ __forceinline__ float lse2(float2 c) {
    return __fadd_rn(fmaxf(c.x, c.y),
                     __logf(__fadd_rn(1.0f, __expf(-fabsf(__fsub_rn(c.x, c.y))))));
}

__device__ __forceinline__ float loc_sl1(float4 ld, float4 a, float4 pr) {
    float gx = ((a.x + a.z) * 0.5f - pr.x) / (0.1f * pr.z);
    float gy = ((a.y + a.w) * 0.5f - pr.y) / (0.1f * pr.w);
    float gw = __logf((a.z - a.x) / pr.z) / 0.2f;
    float gh = __logf((a.w - a.y) / pr.w) / 0.2f;
    float d0 = fabsf(ld.x - gx), d1 = fabsf(ld.y - gy);
    float d2 = fabsf(ld.z - gw), d3 = fabsf(ld.w - gh);
    return (d0 < 1.f ? 0.5f * d0 * d0 : d0 - 0.5f)
         + (d1 < 1.f ? 0.5f * d1 * d1 : d1 - 0.5f)
         + (d2 < 1.f ? 0.5f * d2 * d2 : d2 - 0.5f)
         + (d3 < 1.f ? 0.5f * d3 * d3 : d3 - 0.5f);
}

// Parallel descending radix-select over NB bins.
__device__ __forceinline__ void scan_desc(const int* __restrict__ cnt, int R, int tid,
                                          int* s_w, unsigned* s_idx, int* s_rem,
                                          int* lc_out)
{
    int lane = tid & 31, w = tid >> 5;
    int base = tid * 8;
    int c = 0;
#pragma unroll
    for (int k = 0; k < 8; k++) { lc_out[k] = cnt[NB - 1 - (base + k)]; c += lc_out[k]; }
    int inc = c;
#pragma unroll
    for (int o = 1; o < 32; o <<= 1) {
        int n = __shfl_up_sync(0xFFFFFFFFu, inc, o);
        if (lane >= o) inc += n;
    }
    if (lane == 31) s_w[w] = inc;
    __syncthreads();
    if (tid == 0) {
        int rc = 0;
        for (int i = 0; i < 8; i++) { int v = s_w[i]; s_w[i] = rc; rc += v; }
    }
    __syncthreads();
    int epc = s_w[w] + inc - c;
    if (epc < R && R <= epc + c) {
        int rc = epc;
#pragma unroll
        for (int k = 0; k < 8; k++) {
            int idx = NB - 1 - (base + k);
            if (rc + lc_out[k] >= R) { *s_idx = (unsigned)idx; *s_rem = R - rc; break; }
            rc += lc_out[k];
        }
    }
    __syncthreads();
}

// ---------------- zeroing (3 kernels so k1 is the 4th launch -> profiled) ----------------
__global__ void __launch_bounds__(256) k_zero_a() {
    int g = blockIdx.x * 256 + threadIdx.x;
    for (int i = g; i < BB * NB; i += 16384) ((int*)g_h1c)[i] = 0;
    if (g < BB) { g_poscnt[g] = 0; g_posloss[g] = 0.0; }
    if (g == BB) { g_lossl = 0.0; }
    if (g == BB + 1) { g_ctr = 0; }
}
__global__ void __launch_bounds__(256) k_zero_b() {
    int g = blockIdx.x * 256 + threadIdx.x;
    for (int i = g; i < BB * NB; i += 16384) ((int*)g_h2c)[i] = 0;
    if (g < BB) g_sgt[g] = 0.0;
}
__global__ void __launch_bounds__(256) k_zero_c() {
    int g = blockIdx.x * 256 + threadIdx.x;
    for (int i = g; i < BB * NB; i += 16384) ((int*)g_h3c)[i] = 0;
}

// ---------------- K1: fused match + losses + level-1 histogram (round-2 proven cfg) ----------------
__global__ void __launch_bounds__(BLK) k1(const float4* __restrict__ loc,
                                          const float2* __restrict__ conf,
                                          const float4* __restrict__ priors,
                                          const float*  __restrict__ targets) {
    int b = blockIdx.y, tid = threadIdx.x;
    int lane = tid & 31;
    __shared__ float4 tr[TT];
    __shared__ float  cA[TT];
    __shared__ int    sc[NB];
    __shared__ unsigned long long skey[TT];
    for (int i = tid; i < NB; i += BLK) sc[i] = 0;
    if (tid < TT) {
        const float* tb = targets + (b * TT + tid) * 5;
        float4 v = make_float4(tb[0], tb[1], tb[2], tb[3]);
        tr[tid] = v;
        cA[tid] = __fmul_rn(__fsub_rn(v.z, v.x), __fsub_rn(v.w, v.y));
        skey[tid] = 0ull;
    }
    __syncthreads();

    float ti_[TT], td_[TT]; unsigned tp_[TT];
#pragma unroll
    for (int t = 0; t < TT; t++) { ti_[t] = -1.0f; td_[t] = 1.0f; tp_[t] = 0u; }

    float lossl = 0.0f, ploss = 0.0f;
    int pcnt = 0;
    int pbase = blockIdx.x * (BLK * IPT);
#pragma unroll 1
    for (int i = 0; i < IPT; i++) {
        int p = pbase + i * BLK + tid;
        float4 pr = priors[p];
        float bi, bd; int bti;
        match_one_prior<true>(pr, tr, cA, bi, bd, bti, ti_, td_, tp_, (unsigned)p);

        bool pos = (__fmul_rn(2.0f, bi) >= bd);
        float2 c = conf[(size_t)b * PP + p];
        float lse = lse2(c);
        float mv = pos ? 0.0f : __fsub_rn(lse, c.x);
        unsigned bits = __float_as_uint(mv);
        g_mine[b][p] = bits;
        unsigned bin = bits >> 21;
        unsigned peers = __match_any_sync(0xFFFFFFFFu, bin);
        if (lane == __ffs(peers) - 1) atomicAdd(&sc[bin], __popc(peers));
        if (pos) {
            pcnt++;
            ploss += __fsub_rn(lse, c.y);
            lossl += loc_sl1(loc[(size_t)b * PP + p], tr[bti], pr);
        }
    }

#pragma unroll
    for (int t = 0; t < TT; t++) {
        float iou = ti_[t] / td_[t];
        unsigned long long key =
            ((unsigned long long)__float_as_uint(iou) << 32) |
            (unsigned long long)(0xFFFFFFFFu - tp_[t]);
#pragma unroll
        for (int o = 16; o > 0; o >>= 1) {
            unsigned long long ok = __shfl_down_sync(0xFFFFFFFFu, key, o);
            if (ok > key) key = ok;
        }
        if (lane == 0) atomicMax(&skey[t], key);
    }

#pragma unroll
    for (int o = 16; o > 0; o >>= 1) {
        lossl += __shfl_down_sync(0xFFFFFFFFu, lossl, o);
        ploss += __shfl_down_sync(0xFFFFFFFFu, ploss, o);
        pcnt  += __shfl_down_sync(0xFFFFFFFFu, pcnt, o);
    }
    if (lane == 0) {
        if (lossl != 0.0f) atomicAdd(&g_lossl, (double)lossl);
        if (pcnt) {
            atomicAdd(&g_poscnt[b], pcnt);
            atomicAdd(&g_posloss[b], (double)ploss);
        }
    }
    __syncthreads();
    if (tid < TT) g_bp[b][blockIdx.x][tid] = skey[tid];
    for (int i = tid; i < NB; i += BLK) {
        int cv = sc[i];
        if (cv) atomicAdd(&g_h1c[b][i], cv);
    }
}

// ---------------- K2: best-prior override fixup (warp per batch) ----------------
__global__ void __launch_bounds__(1024) k_fix(const float4* __restrict__ loc,
                                              const float2* __restrict__ conf,
                                              const float4* __restrict__ priors,
                                              const float*  __restrict__ targets) {
    int tid = threadIdx.x;
    int b = tid >> 5, lane = tid & 31;
    __shared__ float4 str[BB][TT];
    __shared__ float  scA[BB][TT];
    if (tid < BB * TT) {
        int bb = tid / TT, t = tid % TT;
        const float* tb = targets + (bb * TT + t) * 5;
        float4 v = make_float4(tb[0], tb[1], tb[2], tb[3]);
        str[bb][t] = v;
        scA[bb][t] = __fmul_rn(__fsub_rn(v.z, v.x), __fsub_rn(v.w, v.y));
    }
    __syncthreads();

    unsigned ps[TT];
#pragma unroll
    for (int t = 0; t < TT; t++) {
        unsigned long long k = (lane < NBLK) ? g_bp[b][lane][t] : 0ull;
#pragma unroll
        for (int o = 16; o > 0; o >>= 1) {
            unsigned long long ok = __shfl_down_sync(0xFFFFFFFFu, k, o);
            if (ok > k) k = ok;
        }
        k = __shfl_sync(0xFFFFFFFFu, k, 0);
        ps[t] = 0xFFFFFFFFu - (unsigned)(k & 0xFFFFFFFFull);
    }
    if (lane != 0) return;

    for (int t = 0; t < TT; t++) {
        bool last = true;
        for (int t2 = t + 1; t2 < TT; t2++)
            if (ps[t2] == ps[t]) { last = false; break; }
        if (!last) continue;                 // last write wins
        unsigned p = ps[t];
        float4 pr = priors[p];
        float bi, bd; int bti;
        match_one_prior<false>(pr, str[b], scA[b], bi, bd, bti, nullptr, nullptr, nullptr, 0u);
        bool pos_old = (__fmul_rn(2.0f, bi) >= bd);
        float2 c = conf[(size_t)b * PP + p];
        float lse = lse2(c);
        float4 ld = loc[(size_t)b * PP + p];
        float sl_new = loc_sl1(ld, str[b][t], pr);
        double dl = 0.0;
        if (pos_old) {
            if (bti != t) dl = (double)sl_new - (double)loc_sl1(ld, str[b][bti], pr);
        } else {
            dl = (double)sl_new;
            g_poscnt[b] += 1;
            g_posloss[b] += (double)__fsub_rn(lse, c.y);
            float mo = __fsub_rn(lse, c.x);      // bit-identical to k1's mv
            unsigned ob = __float_as_uint(mo) >> 21;
            g_h1c[b][ob] -= 1;
            g_h1c[b][0]  += 1;
            g_mine[b][p] = 0u;
        }
        if (dl != 0.0) atomicAdd(&g_lossl, dl);
    }
}

// ---------------- filter A: in-block level-0 select + level-1 histogram ----------------
__global__ void __launch_bounds__(256) k_fa() {
    int b = blockIdx.y, tid = threadIdx.x;
    __shared__ int sc[NB];
    __shared__ int s_w[8];
    __shared__ unsigned s_idx;
    __shared__ int s_rem;
    for (int i = tid; i < NB; i += 256) sc[i] = 0;

    int k3 = 3 * g_poscnt[b];
    int R = (k3 < PP - 1) ? k3 : (PP - 1);
    int lc[8];
    scan_desc(g_h1c[b], R, tid, s_w, &s_idx, &s_rem, lc);
    unsigned pref = s_idx;

    int pbase = blockIdx.x * (256 * IPTF);
#pragma unroll
    for (int i = 0; i < IPTF; i++) {
        unsigned bits = g_mine[b][pbase + i * 256 + tid];
        if ((bits >> 21) == pref) atomicAdd(&sc[(bits >> 10) & 0x7FFu], 1);
    }
    __syncthreads();
    for (int i = tid; i < NB; i += 256)
        if (sc[i]) atomicAdd(&g_h2c[b][i], sc[i]);
    if (tid == 0) { g_pref0[b] = pref; g_R1[b] = s_rem; }
}

// ---------------- filter B: in-block level-1 select + level-2 hist + upper sum ----------------
__global__ void __launch_bounds__(256) k_fb() {
    int b = blockIdx.y, tid = threadIdx.x, lane = tid & 31;
    __shared__ int sc[NB];
    __shared__ int s_w[8];
    __shared__ unsigned s_idx;
    __shared__ int s_rem;
    for (int i = tid; i < NB; i += 256) sc[i] = 0;

    int lc[8];
    scan_desc(g_h2c[b], g_R1[b], tid, s_w, &s_idx, &s_rem, lc);
    unsigned pref22 = (g_pref0[b] << 11) | s_idx;

    float fsum = 0.0f;
    int pbase = blockIdx.x * (256 * IPTF);
#pragma unroll
    for (int i = 0; i < IPTF; i++) {
        unsigned bits = g_mine[b][pbase + i * 256 + tid];
        unsigned top = bits >> 10;
        if (top == pref22) atomicAdd(&sc[bits & 0x3FFu], 1);
        else if (top > pref22) fsum += __uint_as_float(bits);
    }
    __syncthreads();
    for (int i = tid; i < NB; i += 256)
        if (sc[i]) atomicAdd(&g_h3c[b][i], sc[i]);
#pragma unroll
    for (int o = 16; o > 0; o >>= 1)
        fsum += __shfl_down_sync(0xFFFFFFFFu, fsum, o);
    if (lane == 0 && fsum != 0.0f) atomicAdd(&g_sgt[b], (double)fsum);
    if (tid == 0) { g_pref22[b] = pref22; g_R2[b] = s_rem; }
}

// ---------------- last: level-2 select + exact top-K sum + final combine ----------------
__global__ void __launch_bounds__(256) k_last(float* __restrict__ out) {
    int b = blockIdx.x, tid = threadIdx.x;
    __shared__ int s_w[8];
    __shared__ unsigned s_idx;
    __shared__ int s_rem;
    __shared__ double wsum[8];
    __shared__ int s_last;

    int lc[8];
    scan_desc(g_h3c[b], g_R2[b], tid, s_w, &s_idx, &s_rem, lc);
    unsigned pref = g_pref22[b];
    unsigned idx3 = s_idx;
    int R3 = s_rem;

    double s = 0.0;
    int base = tid * 8;
#pragma unroll
    for (int k = 0; k < 8; k++) {
        unsigned idx = (unsigned)(NB - 1 - (base + k));
        if (idx > idx3 && lc[k])
            s += (double)lc[k] * (double)__uint_as_float((pref << 10) | idx);
    }
#pragma unroll
    for (int o = 16; o > 0; o >>= 1)
        s += __shfl_down_sync(0xFFFFFFFFu, s, o);
    if ((tid & 31) == 0) wsum[tid >> 5] = s;
    __syncthreads();
    if (tid == 0) {
        double tot = 0.0;
        for (int w = 0; w < 8; w++) tot += wsum[w];
        g_topsum[b] = g_sgt[b] + tot +
                      (double)R3 * (double)__uint_as_float((pref << 10) | idx3);
        __threadfence();
        int done = atomicAdd(&g_ctr, 1);
        s_last = (done == BB - 1) ? 1 : 0;
    }
    __syncthreads();
    if (s_last) {
        __threadfence();
        if (tid < 32) {
            int np = g_poscnt[tid];
            double lc2 = g_posloss[tid] + g_topsum[tid];
#pragma unroll
            for (int o = 16; o > 0; o >>= 1) {
                np  += __shfl_down_sync(0xFFFFFFFFu, np, o);
                lc2 += __shfl_down_sync(0xFFFFFFFFu, lc2, o);
            }
            if (tid == 0) {
                double N = (double)np;
                out[0] = (float)(g_lossl / N);
                out[1] = (float)(lc2 / N);
            }
        }
    }
}

// ---------------- launch ----------------
extern "C" void kernel_launch(void* const* d_in, const int* in_sizes, int n_in,
                              void* d_out, int out_size) {
    const float4* loc     = (const float4*)d_in[0];
    const float2* conf    = (const float2*)d_in[1];
    const float4* priors  = (const float4*)d_in[2];
    const float*  targets = (const float*)d_in[3];
    float* out = (float*)d_out;

    k_zero_a<<<64, 256>>>();
    k_zero_b<<<64, 256>>>();
    k_zero_c<<<64, 256>>>();
    dim3 g1(NBLK, BB);
    k1<<<g1, BLK>>>(loc, conf, priors, targets);   // 4th launch -> ncu captures this
    k_fix<<<1, 1024>>>(loc, conf, priors, targets);
    dim3 gf(NBLKF, BB);
    k_fa<<<gf, 256>>>();
    k_fb<<<gf, 256>>>();
    k_last<<<BB, 256>>>(out);
}